// round 10
// baseline (speedup 1.0000x reference)
#include <cuda_runtime.h>

#define NTH  256

struct Params { const float* p[27]; };

// Exact leaky-relu slope 0.0025: rr(v) = max(v, 0.0025*v).
// FMUL (fma pipe) + FMNMX (alu pipe), no predicates.
__device__ __forceinline__ float rr(float v) {
    return fmaxf(v, 0.0025f * v);
}

// ---- shared layout (floats); every W/b offset 16B-aligned for LDS.128 ----
// W_in stored TRANSPOSED: s[j*8+i] = W_in[i][j]
#define O_WIN_T  0      // 64
#define O_B_IN   64     // 8
#define O_W_H1   72     // [8][4] row-major, 32
#define O_B_H1   104    // 4
#define O_W_H2   108
#define O_B_H2   124
#define O_W_H3   128
#define O_B_H3   144
#define O_W_H4   148
#define O_B_H4   164
#define O_W_H5   168
#define O_B_H5   184
#define O_W_EN   188    // 4
#define O_B_EN   192    // 1 (+3 pad)
#define O_W_H6   196    // 4
#define O_B_H6   200    // 4
#define O_W_H7   204
#define O_B_H7   220
#define O_W_H8   224
#define O_B_H8   240
#define O_W_H9   244
#define O_B_H9   260
#define O_W_HA   264
#define O_B_HA   280
#define O_W_DE   284    // [4][8] row-major, 32
#define O_B_DE   316    // 8
#define S_TOTAL  324

__device__ __forceinline__ float4 ld4(const float* s, int off) {
    return *reinterpret_cast<const float4*>(s + off);
}

// 4x4 layer for 2 rows, j-vectorized: 5 LDS.128 total.
template<bool ACT, bool RESID>
__device__ __forceinline__ void lin44(const float* __restrict__ s, int Woff, int boff,
                                      const float (&src)[2][4], float (&dst)[2][4]) {
    float4 b = ld4(s, boff);
    float acc[2][4];
#pragma unroll
    for (int r = 0; r < 2; r++) {
        acc[r][0] = b.x; acc[r][1] = b.y; acc[r][2] = b.z; acc[r][3] = b.w;
    }
#pragma unroll
    for (int i = 0; i < 4; i++) {
        float4 w = ld4(s, Woff + 4 * i);
#pragma unroll
        for (int r = 0; r < 2; r++) {
            acc[r][0] = fmaf(src[r][i], w.x, acc[r][0]);
            acc[r][1] = fmaf(src[r][i], w.y, acc[r][1]);
            acc[r][2] = fmaf(src[r][i], w.z, acc[r][2]);
            acc[r][3] = fmaf(src[r][i], w.w, acc[r][3]);
        }
    }
#pragma unroll
    for (int r = 0; r < 2; r++)
#pragma unroll
        for (int j = 0; j < 4; j++)
            dst[r][j] = RESID ? (dst[r][j] + acc[r][j]) : (ACT ? rr(acc[r][j]) : acc[r][j]);
}

template<bool GUARD>
__global__ __launch_bounds__(NTH, 5)
void ann_fused_kernel(Params P, float* __restrict__ out, int N) {
    __shared__ alignas(16) float s[S_TOTAL];

    // ---- cooperative weight staging (once per block) ----
    {
        const float* win = P.p[1];
        for (int idx = threadIdx.x; idx < 64; idx += NTH) {
            int i = idx >> 3, j = idx & 7;
            s[O_WIN_T + j * 8 + i] = win[idx];   // transpose W_in
        }
        const short off[25] = {O_B_IN,O_W_H1,O_B_H1,O_W_H2,O_B_H2,O_W_H3,O_B_H3,
                               O_W_H4,O_B_H4,O_W_H5,O_B_H5,O_W_EN,O_B_EN,O_W_H6,O_B_H6,
                               O_W_H7,O_B_H7,O_W_H8,O_B_H8,O_W_H9,O_B_H9,O_W_HA,O_B_HA,
                               O_W_DE,O_B_DE};
        const short cnt[25] = {8,32,4,16,4,16,4,16,4,16,4,4,1,4,4,16,4,16,4,16,4,16,4,32,8};
        for (int k = 0; k < 25; k++) {
            const float* src = P.p[k + 2];
            for (int i = threadIdx.x; i < cnt[k]; i += NTH) s[off[k] + i] = src[i];
        }
    }
    __syncthreads();

    const float* __restrict__ xin = P.p[0];
    unsigned base = blockIdx.x * (2 * NTH) + threadIdx.x;
    unsigned rA = base, rB = base + NTH;

    // ---- load 2 rows (streaming, coalesced float4) ----
    float xa[8], xb[8];
    if (!GUARD || rA < (unsigned)N) {
        float4 a0 = __ldcs(reinterpret_cast<const float4*>(xin + (size_t)rA * 8));
        float4 a1 = __ldcs(reinterpret_cast<const float4*>(xin + (size_t)rA * 8 + 4));
        xa[0]=a0.x; xa[1]=a0.y; xa[2]=a0.z; xa[3]=a0.w;
        xa[4]=a1.x; xa[5]=a1.y; xa[6]=a1.z; xa[7]=a1.w;
    } else {
#pragma unroll
        for (int i = 0; i < 8; i++) xa[i] = 0.f;
    }
    if (!GUARD || rB < (unsigned)N) {
        float4 b0 = __ldcs(reinterpret_cast<const float4*>(xin + (size_t)rB * 8));
        float4 b1 = __ldcs(reinterpret_cast<const float4*>(xin + (size_t)rB * 8 + 4));
        xb[0]=b0.x; xb[1]=b0.y; xb[2]=b0.z; xb[3]=b0.w;
        xb[4]=b1.x; xb[5]=b1.y; xb[6]=b1.z; xb[7]=b1.w;
    } else {
#pragma unroll
        for (int i = 0; i < 8; i++) xb[i] = 0.f;
    }

    // ---- fused in+h1, column-wise over the 8 hidden units ----
    float x[2][4], t[2][4];
    {
        float4 bh1 = ld4(s, O_B_H1);
        x[0][0]=bh1.x; x[0][1]=bh1.y; x[0][2]=bh1.z; x[0][3]=bh1.w;
        x[1][0]=bh1.x; x[1][1]=bh1.y; x[1][2]=bh1.z; x[1][3]=bh1.w;
#pragma unroll
        for (int j = 0; j < 8; j++) {
            float bj = s[O_B_IN + j];
            float4 w0 = ld4(s, O_WIN_T + j * 8);
            float4 w1 = ld4(s, O_WIN_T + j * 8 + 4);
            float va = bj, vb = bj;
            va = fmaf(xa[0], w0.x, va); vb = fmaf(xb[0], w0.x, vb);
            va = fmaf(xa[1], w0.y, va); vb = fmaf(xb[1], w0.y, vb);
            va = fmaf(xa[2], w0.z, va); vb = fmaf(xb[2], w0.z, vb);
            va = fmaf(xa[3], w0.w, va); vb = fmaf(xb[3], w0.w, vb);
            va = fmaf(xa[4], w1.x, va); vb = fmaf(xb[4], w1.x, vb);
            va = fmaf(xa[5], w1.y, va); vb = fmaf(xb[5], w1.y, vb);
            va = fmaf(xa[6], w1.z, va); vb = fmaf(xb[6], w1.z, vb);
            va = fmaf(xa[7], w1.w, va); vb = fmaf(xb[7], w1.w, vb);
            va = rr(va); vb = rr(vb);
            float4 h = ld4(s, O_W_H1 + j * 4);
            x[0][0] = fmaf(va, h.x, x[0][0]); x[1][0] = fmaf(vb, h.x, x[1][0]);
            x[0][1] = fmaf(va, h.y, x[0][1]); x[1][1] = fmaf(vb, h.y, x[1][1]);
            x[0][2] = fmaf(va, h.z, x[0][2]); x[1][2] = fmaf(vb, h.z, x[1][2]);
            x[0][3] = fmaf(va, h.w, x[0][3]); x[1][3] = fmaf(vb, h.w, x[1][3]);
        }
    }

    // ---- encoder residual blocks ----
    lin44<true,  false>(s, O_W_H2, O_B_H2, x, t);
    lin44<false, true >(s, O_W_H3, O_B_H3, t, x);
    lin44<true,  false>(s, O_W_H4, O_B_H4, x, t);
    lin44<false, true >(s, O_W_H5, O_B_H5, t, x);

    // ---- encode (4 -> 1) + store ----
    float e[2];
    {
        float4 we = ld4(s, O_W_EN);
        float be = s[O_B_EN];
#pragma unroll
        for (int r = 0; r < 2; r++) {
            float v = be;
            v = fmaf(x[r][0], we.x, v); v = fmaf(x[r][1], we.y, v);
            v = fmaf(x[r][2], we.z, v); v = fmaf(x[r][3], we.w, v);
            e[r] = rr(v);
        }
    }
    if (!GUARD || rA < (unsigned)N) __stcs(out + rA, e[0]);
    if (!GUARD || rB < (unsigned)N) __stcs(out + rB, e[1]);

    // ---- h6 (1 -> 4) ----
    {
        float4 w6 = ld4(s, O_W_H6);
        float4 b6 = ld4(s, O_B_H6);
#pragma unroll
        for (int r = 0; r < 2; r++) {
            x[r][0] = rr(fmaf(e[r], w6.x, b6.x));
            x[r][1] = rr(fmaf(e[r], w6.y, b6.y));
            x[r][2] = rr(fmaf(e[r], w6.z, b6.z));
            x[r][3] = rr(fmaf(e[r], w6.w, b6.w));
        }
    }

    // ---- decoder residual blocks ----
    lin44<true,  false>(s, O_W_H7, O_B_H7, x, t);
    lin44<false, true >(s, O_W_H8, O_B_H8, t, x);
    lin44<true,  false>(s, O_W_H9, O_B_H9, x, t);
    lin44<false, true >(s, O_W_HA, O_B_HA, t, x);

    // ---- decode (4 -> 8) + store, one row at a time (low tail liveness) ----
    float* __restrict__ dec = out + N;
#pragma unroll
    for (int r = 0; r < 2; r++) {
        float4 b0 = ld4(s, O_B_DE);
        float4 b1 = ld4(s, O_B_DE + 4);
        float d[8];
        d[0]=b0.x; d[1]=b0.y; d[2]=b0.z; d[3]=b0.w;
        d[4]=b1.x; d[5]=b1.y; d[6]=b1.z; d[7]=b1.w;
#pragma unroll
        for (int i = 0; i < 4; i++) {
            float4 w0 = ld4(s, O_W_DE + i * 8);
            float4 w1 = ld4(s, O_W_DE + i * 8 + 4);
            float v = x[r][i];
            d[0] = fmaf(v, w0.x, d[0]); d[1] = fmaf(v, w0.y, d[1]);
            d[2] = fmaf(v, w0.z, d[2]); d[3] = fmaf(v, w0.w, d[3]);
            d[4] = fmaf(v, w1.x, d[4]); d[5] = fmaf(v, w1.y, d[5]);
            d[6] = fmaf(v, w1.z, d[6]); d[7] = fmaf(v, w1.w, d[7]);
        }
        unsigned row = (r == 0) ? rA : rB;
        if (!GUARD || row < (unsigned)N) {
            __stcs(reinterpret_cast<float4*>(dec + (size_t)row * 8),
                   make_float4(rr(d[0]), rr(d[1]), rr(d[2]), rr(d[3])));
            __stcs(reinterpret_cast<float4*>(dec + (size_t)row * 8 + 4),
                   make_float4(rr(d[4]), rr(d[5]), rr(d[6]), rr(d[7])));
        }
    }
}

extern "C" void kernel_launch(void* const* d_in, const int* in_sizes, int n_in,
                              void* d_out, int out_size) {
    Params P;
    for (int k = 0; k < 27; k++) P.p[k] = (const float*)d_in[k];
    int N = in_sizes[0] / 8;                 // 4194304 rows
    int rows_per_block = 2 * NTH;            // 512
    int blocks = (N + rows_per_block - 1) / rows_per_block;
    if (N % rows_per_block == 0)
        ann_fused_kernel<false><<<blocks, NTH>>>(P, (float*)d_out, N);
    else
        ann_fused_kernel<true ><<<blocks, NTH>>>(P, (float*)d_out, N);
}

// round 11
// speedup vs baseline: 2.2383x; 2.2383x over previous
#include <cuda_runtime.h>

#define NTH  256

struct Params { const float* p[27]; };

// Exact leaky-relu slope 0.0025: rr(v) = max(v, 0.0025*v).
__device__ __forceinline__ float rr(float v) {
    return fmaxf(v, 0.0025f * v);
}

// ---- constant-memory layout (floats); W/b offsets 16B-aligned for LDC.128 ----
// W_in stored TRANSPOSED: c_s[j*8+i] = W_in[i][j]
#define O_WIN_T  0      // 64
#define O_B_IN   64     // 8
#define O_W_H1   72     // [8][4] row-major, 32
#define O_B_H1   104    // 4
#define O_W_H2   108
#define O_B_H2   124
#define O_W_H3   128
#define O_B_H3   144
#define O_W_H4   148
#define O_B_H4   164
#define O_W_H5   168
#define O_B_H5   184
#define O_W_EN   188    // 4
#define O_B_EN   192    // 1 (+3 pad)
#define O_W_H6   196    // 4
#define O_B_H6   200    // 4
#define O_W_H7   204
#define O_B_H7   220
#define O_W_H8   224
#define O_B_H8   240
#define O_W_H9   244
#define O_B_H9   260
#define O_W_HA   264
#define O_B_HA   280
#define O_W_DE   284    // [4][8] row-major, 32
#define O_B_DE   316    // 8
#define S_TOTAL  324

__constant__ float c_s[S_TOTAL];
__device__   float g_stage[S_TOTAL];   // static scratch (no allocation)

// Gather + layout kernel: packs the 26 weight arrays into g_stage once per replay.
__global__ void gather_weights(Params P) {
    int tid = threadIdx.x;
    // transpose W_in: g[j*8+i] = W_in[i*8+j]
    if (tid < 64) {
        int i = tid >> 3, j = tid & 7;
        g_stage[O_WIN_T + j * 8 + i] = P.p[1][tid];
    }
    const short off[25] = {O_B_IN,O_W_H1,O_B_H1,O_W_H2,O_B_H2,O_W_H3,O_B_H3,
                           O_W_H4,O_B_H4,O_W_H5,O_B_H5,O_W_EN,O_B_EN,O_W_H6,O_B_H6,
                           O_W_H7,O_B_H7,O_W_H8,O_B_H8,O_W_H9,O_B_H9,O_W_HA,O_B_HA,
                           O_W_DE,O_B_DE};
    const short cnt[25] = {8,32,4,16,4,16,4,16,4,16,4,4,1,4,4,16,4,16,4,16,4,16,4,32,8};
    for (int k = 0; k < 25; k++) {
        const float* src = P.p[k + 2];
        for (int i = tid; i < cnt[k]; i += NTH) g_stage[off[k] + i] = src[i];
    }
}

__device__ __forceinline__ float4 ld4c(int off) {
    return *reinterpret_cast<const float4*>(c_s + off);
}

// 4x4 layer for 4 rows, j-vectorized: 5 LDC.128 total (const port, not LSU).
template<bool ACT, bool RESID>
__device__ __forceinline__ void lin44(int Woff, int boff,
                                      const float (&src)[4][4], float (&dst)[4][4]) {
    float4 b = ld4c(boff);
    float acc[4][4];
#pragma unroll
    for (int r = 0; r < 4; r++) {
        acc[r][0] = b.x; acc[r][1] = b.y; acc[r][2] = b.z; acc[r][3] = b.w;
    }
#pragma unroll
    for (int i = 0; i < 4; i++) {
        float4 w = ld4c(Woff + 4 * i);
#pragma unroll
        for (int r = 0; r < 4; r++) {
            acc[r][0] = fmaf(src[r][i], w.x, acc[r][0]);
            acc[r][1] = fmaf(src[r][i], w.y, acc[r][1]);
            acc[r][2] = fmaf(src[r][i], w.z, acc[r][2]);
            acc[r][3] = fmaf(src[r][i], w.w, acc[r][3]);
        }
    }
#pragma unroll
    for (int r = 0; r < 4; r++)
#pragma unroll
        for (int j = 0; j < 4; j++)
            dst[r][j] = RESID ? (dst[r][j] + acc[r][j]) : (ACT ? rr(acc[r][j]) : acc[r][j]);
}

template<bool GUARD>
__global__ __launch_bounds__(NTH, 4)
void ann_fused_kernel(const float* __restrict__ xin, float* __restrict__ out, int N) {
    unsigned base = blockIdx.x * (4 * NTH) + threadIdx.x;

    // ---- fused in+h1, processed 2 rows at a time to cap register liveness ----
    float x[4][4];
    {
        float4 bh1 = ld4c(O_B_H1);
#pragma unroll
        for (int r = 0; r < 4; r++) {
            x[r][0]=bh1.x; x[r][1]=bh1.y; x[r][2]=bh1.z; x[r][3]=bh1.w;
        }
#pragma unroll
        for (int pp = 0; pp < 2; pp++) {
            unsigned rA = base + (2 * pp) * NTH;
            unsigned rB = rA + NTH;
            float xa[8], xb[8];
            if (!GUARD || rA < (unsigned)N) {
                float4 a0 = __ldcs(reinterpret_cast<const float4*>(xin + (size_t)rA * 8));
                float4 a1 = __ldcs(reinterpret_cast<const float4*>(xin + (size_t)rA * 8 + 4));
                xa[0]=a0.x; xa[1]=a0.y; xa[2]=a0.z; xa[3]=a0.w;
                xa[4]=a1.x; xa[5]=a1.y; xa[6]=a1.z; xa[7]=a1.w;
            } else {
#pragma unroll
                for (int i = 0; i < 8; i++) xa[i] = 0.f;
            }
            if (!GUARD || rB < (unsigned)N) {
                float4 b0 = __ldcs(reinterpret_cast<const float4*>(xin + (size_t)rB * 8));
                float4 b1 = __ldcs(reinterpret_cast<const float4*>(xin + (size_t)rB * 8 + 4));
                xb[0]=b0.x; xb[1]=b0.y; xb[2]=b0.z; xb[3]=b0.w;
                xb[4]=b1.x; xb[5]=b1.y; xb[6]=b1.z; xb[7]=b1.w;
            } else {
#pragma unroll
                for (int i = 0; i < 8; i++) xb[i] = 0.f;
            }
#pragma unroll
            for (int j = 0; j < 8; j++) {
                float bj = c_s[O_B_IN + j];
                float4 w0 = ld4c(O_WIN_T + j * 8);
                float4 w1 = ld4c(O_WIN_T + j * 8 + 4);
                float va = bj, vb = bj;
                va = fmaf(xa[0], w0.x, va); vb = fmaf(xb[0], w0.x, vb);
                va = fmaf(xa[1], w0.y, va); vb = fmaf(xb[1], w0.y, vb);
                va = fmaf(xa[2], w0.z, va); vb = fmaf(xb[2], w0.z, vb);
                va = fmaf(xa[3], w0.w, va); vb = fmaf(xb[3], w0.w, vb);
                va = fmaf(xa[4], w1.x, va); vb = fmaf(xb[4], w1.x, vb);
                va = fmaf(xa[5], w1.y, va); vb = fmaf(xb[5], w1.y, vb);
                va = fmaf(xa[6], w1.z, va); vb = fmaf(xb[6], w1.z, vb);
                va = fmaf(xa[7], w1.w, va); vb = fmaf(xb[7], w1.w, vb);
                va = rr(va); vb = rr(vb);
                float4 h = ld4c(O_W_H1 + j * 4);
                x[2*pp  ][0] = fmaf(va, h.x, x[2*pp  ][0]);
                x[2*pp  ][1] = fmaf(va, h.y, x[2*pp  ][1]);
                x[2*pp  ][2] = fmaf(va, h.z, x[2*pp  ][2]);
                x[2*pp  ][3] = fmaf(va, h.w, x[2*pp  ][3]);
                x[2*pp+1][0] = fmaf(vb, h.x, x[2*pp+1][0]);
                x[2*pp+1][1] = fmaf(vb, h.y, x[2*pp+1][1]);
                x[2*pp+1][2] = fmaf(vb, h.z, x[2*pp+1][2]);
                x[2*pp+1][3] = fmaf(vb, h.w, x[2*pp+1][3]);
            }
        }
    }

    float t[4][4];

    // ---- encoder residual blocks ----
    lin44<true,  false>(O_W_H2, O_B_H2, x, t);
    lin44<false, true >(O_W_H3, O_B_H3, t, x);
    lin44<true,  false>(O_W_H4, O_B_H4, x, t);
    lin44<false, true >(O_W_H5, O_B_H5, t, x);

    // ---- encode (4 -> 1) + store ----
    float e[4];
    {
        float4 we = ld4c(O_W_EN);
        float be = c_s[O_B_EN];
#pragma unroll
        for (int r = 0; r < 4; r++) {
            float v = be;
            v = fmaf(x[r][0], we.x, v); v = fmaf(x[r][1], we.y, v);
            v = fmaf(x[r][2], we.z, v); v = fmaf(x[r][3], we.w, v);
            e[r] = rr(v);
        }
    }
#pragma unroll
    for (int r = 0; r < 4; r++) {
        unsigned row = base + r * NTH;
        if (!GUARD || row < (unsigned)N) __stcs(out + row, e[r]);
    }

    // ---- h6 (1 -> 4) ----
    {
        float4 w6 = ld4c(O_W_H6);
        float4 b6 = ld4c(O_B_H6);
#pragma unroll
        for (int r = 0; r < 4; r++) {
            x[r][0] = rr(fmaf(e[r], w6.x, b6.x));
            x[r][1] = rr(fmaf(e[r], w6.y, b6.y));
            x[r][2] = rr(fmaf(e[r], w6.z, b6.z));
            x[r][3] = rr(fmaf(e[r], w6.w, b6.w));
        }
    }

    // ---- decoder residual blocks ----
    lin44<true,  false>(O_W_H7, O_B_H7, x, t);
    lin44<false, true >(O_W_H8, O_B_H8, t, x);
    lin44<true,  false>(O_W_H9, O_B_H9, x, t);
    lin44<false, true >(O_W_HA, O_B_HA, t, x);

    // ---- decode (4 -> 8) + store, 2 rows at a time (low tail liveness) ----
    float* __restrict__ dec = out + N;
#pragma unroll
    for (int pp = 0; pp < 2; pp++) {
        float4 b0 = ld4c(O_B_DE);
        float4 b1 = ld4c(O_B_DE + 4);
        float da[8], db[8];
        da[0]=b0.x; da[1]=b0.y; da[2]=b0.z; da[3]=b0.w;
        da[4]=b1.x; da[5]=b1.y; da[6]=b1.z; da[7]=b1.w;
#pragma unroll
        for (int j = 0; j < 8; j++) db[j] = da[j];
#pragma unroll
        for (int i = 0; i < 4; i++) {
            float4 w0 = ld4c(O_W_DE + i * 8);
            float4 w1 = ld4c(O_W_DE + i * 8 + 4);
            float va = x[2*pp][i], vb = x[2*pp+1][i];
            da[0] = fmaf(va, w0.x, da[0]); db[0] = fmaf(vb, w0.x, db[0]);
            da[1] = fmaf(va, w0.y, da[1]); db[1] = fmaf(vb, w0.y, db[1]);
            da[2] = fmaf(va, w0.z, da[2]); db[2] = fmaf(vb, w0.z, db[2]);
            da[3] = fmaf(va, w0.w, da[3]); db[3] = fmaf(vb, w0.w, db[3]);
            da[4] = fmaf(va, w1.x, da[4]); db[4] = fmaf(vb, w1.x, db[4]);
            da[5] = fmaf(va, w1.y, da[5]); db[5] = fmaf(vb, w1.y, db[5]);
            da[6] = fmaf(va, w1.z, da[6]); db[6] = fmaf(vb, w1.z, db[6]);
            da[7] = fmaf(va, w1.w, da[7]); db[7] = fmaf(vb, w1.w, db[7]);
        }
        unsigned rA = base + (2 * pp) * NTH;
        unsigned rB = rA + NTH;
        if (!GUARD || rA < (unsigned)N) {
            __stcs(reinterpret_cast<float4*>(dec + (size_t)rA * 8),
                   make_float4(rr(da[0]), rr(da[1]), rr(da[2]), rr(da[3])));
            __stcs(reinterpret_cast<float4*>(dec + (size_t)rA * 8 + 4),
                   make_float4(rr(da[4]), rr(da[5]), rr(da[6]), rr(da[7])));
        }
        if (!GUARD || rB < (unsigned)N) {
            __stcs(reinterpret_cast<float4*>(dec + (size_t)rB * 8),
                   make_float4(rr(db[0]), rr(db[1]), rr(db[2]), rr(db[3])));
            __stcs(reinterpret_cast<float4*>(dec + (size_t)rB * 8 + 4),
                   make_float4(rr(db[4]), rr(db[5]), rr(db[6]), rr(db[7])));
        }
    }
}

extern "C" void kernel_launch(void* const* d_in, const int* in_sizes, int n_in,
                              void* d_out, int out_size) {
    Params P;
    for (int k = 0; k < 27; k++) P.p[k] = (const float*)d_in[k];
    int N = in_sizes[0] / 8;                 // 4194304 rows

    // 1) pack weights into staging buffer (device), 2) copy into __constant__,
    // 3) run the fused kernel. All graph-capturable stream ops, no allocation.
    gather_weights<<<1, NTH>>>(P);
    void* stage_ptr = nullptr;
    cudaGetSymbolAddress(&stage_ptr, g_stage);
    cudaMemcpyToSymbolAsync(c_s, stage_ptr, S_TOTAL * sizeof(float), 0,
                            cudaMemcpyDeviceToDevice, 0);

    int rows_per_block = 4 * NTH;            // 1024
    int blocks = (N + rows_per_block - 1) / rows_per_block;
    if (N % rows_per_block == 0)
        ann_fused_kernel<false><<<blocks, NTH>>>((const float*)d_in[0], (float*)d_out, N);
    else
        ann_fused_kernel<true ><<<blocks, NTH>>>((const float*)d_in[0], (float*)d_out, N);
}

// round 12
// speedup vs baseline: 2.3834x; 1.0648x over previous
#include <cuda_runtime.h>

#define NTH  256

struct Params { const float* p[27]; };

// Exact leaky-relu slope 0.0025: rr(v) = max(v, 0.0025*v).
__device__ __forceinline__ float rr(float v) {
    return fmaxf(v, 0.0025f * v);
}

// ---- constant-memory layout (floats); W/b offsets 16B-aligned for LDC.128 ----
// W_in stored TRANSPOSED: c_s[j*8+i] = W_in[i][j]
#define O_WIN_T  0      // 64
#define O_B_IN   64     // 8
#define O_W_H1   72     // [8][4] row-major, 32
#define O_B_H1   104    // 4
#define O_W_H2   108
#define O_B_H2   124
#define O_W_H3   128
#define O_B_H3   144
#define O_W_H4   148
#define O_B_H4   164
#define O_W_H5   168
#define O_B_H5   184
#define O_W_EN   188    // 4
#define O_B_EN   192    // 1 (+3 pad)
#define O_W_H6   196    // 4
#define O_B_H6   200    // 4
#define O_W_H7   204
#define O_B_H7   220
#define O_W_H8   224
#define O_B_H8   240
#define O_W_H9   244
#define O_B_H9   260
#define O_W_HA   264
#define O_B_HA   280
#define O_W_DE   284    // [4][8] row-major, 32
#define O_B_DE   316    // 8
#define S_TOTAL  324

__constant__ float c_s[S_TOTAL];
__device__   float g_stage[S_TOTAL];   // static scratch (no allocation)

// Fully parallel gather: one thread per destination slot, one LDG + one STG each.
// All 324 loads issue concurrently -> ~1 memory round trip total.
__global__ void gather_weights(Params P) {
    int i = threadIdx.x;
    if (i >= S_TOTAL) return;

    float v = 0.f;                       // pad slots (193..195) -> 0
    if (i < O_B_IN) {
        // transposed W_in: dst j*8+ii  <-  src ii*8+j
        int j = i >> 3, ii = i & 7;
        v = P.p[1][ii * 8 + j];
    } else {
        // segment search over the 25 remaining params
        const short off[26] = {O_B_IN,O_W_H1,O_B_H1,O_W_H2,O_B_H2,O_W_H3,O_B_H3,
                               O_W_H4,O_B_H4,O_W_H5,O_B_H5,O_W_EN,O_B_EN,O_W_H6,O_B_H6,
                               O_W_H7,O_B_H7,O_W_H8,O_B_H8,O_W_H9,O_B_H9,O_W_HA,O_B_HA,
                               O_W_DE,O_B_DE,S_TOTAL};
        const short cnt[25] = {8,32,4,16,4,16,4,16,4,16,4,4,1,4,4,16,4,16,4,16,4,16,4,32,8};
#pragma unroll
        for (int k = 0; k < 25; k++) {
            int rel = i - off[k];
            if (rel >= 0 && rel < cnt[k]) v = P.p[k + 2][rel];
        }
    }
    g_stage[i] = v;
}

__device__ __forceinline__ float4 ld4c(int off) {
    return *reinterpret_cast<const float4*>(c_s + off);
}

// 4x4 layer for 4 rows, j-vectorized: 5 LDC.128 total (const port, not LSU).
template<bool ACT, bool RESID>
__device__ __forceinline__ void lin44(int Woff, int boff,
                                      const float (&src)[4][4], float (&dst)[4][4]) {
    float4 b = ld4c(boff);
    float acc[4][4];
#pragma unroll
    for (int r = 0; r < 4; r++) {
        acc[r][0] = b.x; acc[r][1] = b.y; acc[r][2] = b.z; acc[r][3] = b.w;
    }
#pragma unroll
    for (int i = 0; i < 4; i++) {
        float4 w = ld4c(Woff + 4 * i);
#pragma unroll
        for (int r = 0; r < 4; r++) {
            acc[r][0] = fmaf(src[r][i], w.x, acc[r][0]);
            acc[r][1] = fmaf(src[r][i], w.y, acc[r][1]);
            acc[r][2] = fmaf(src[r][i], w.z, acc[r][2]);
            acc[r][3] = fmaf(src[r][i], w.w, acc[r][3]);
        }
    }
#pragma unroll
    for (int r = 0; r < 4; r++)
#pragma unroll
        for (int j = 0; j < 4; j++)
            dst[r][j] = RESID ? (dst[r][j] + acc[r][j]) : (ACT ? rr(acc[r][j]) : acc[r][j]);
}

template<bool GUARD>
__global__ __launch_bounds__(NTH, 4)
void ann_fused_kernel(const float* __restrict__ xin, float* __restrict__ out, int N) {
    unsigned base = blockIdx.x * (4 * NTH) + threadIdx.x;

    // ---- fused in+h1, processed 2 rows at a time to cap register liveness ----
    float x[4][4];
    {
        float4 bh1 = ld4c(O_B_H1);
#pragma unroll
        for (int r = 0; r < 4; r++) {
            x[r][0]=bh1.x; x[r][1]=bh1.y; x[r][2]=bh1.z; x[r][3]=bh1.w;
        }
#pragma unroll
        for (int pp = 0; pp < 2; pp++) {
            unsigned rA = base + (2 * pp) * NTH;
            unsigned rB = rA + NTH;
            float xa[8], xb[8];
            if (!GUARD || rA < (unsigned)N) {
                float4 a0 = __ldcs(reinterpret_cast<const float4*>(xin + (size_t)rA * 8));
                float4 a1 = __ldcs(reinterpret_cast<const float4*>(xin + (size_t)rA * 8 + 4));
                xa[0]=a0.x; xa[1]=a0.y; xa[2]=a0.z; xa[3]=a0.w;
                xa[4]=a1.x; xa[5]=a1.y; xa[6]=a1.z; xa[7]=a1.w;
            } else {
#pragma unroll
                for (int i = 0; i < 8; i++) xa[i] = 0.f;
            }
            if (!GUARD || rB < (unsigned)N) {
                float4 b0 = __ldcs(reinterpret_cast<const float4*>(xin + (size_t)rB * 8));
                float4 b1 = __ldcs(reinterpret_cast<const float4*>(xin + (size_t)rB * 8 + 4));
                xb[0]=b0.x; xb[1]=b0.y; xb[2]=b0.z; xb[3]=b0.w;
                xb[4]=b1.x; xb[5]=b1.y; xb[6]=b1.z; xb[7]=b1.w;
            } else {
#pragma unroll
                for (int i = 0; i < 8; i++) xb[i] = 0.f;
            }
#pragma unroll
            for (int j = 0; j < 8; j++) {
                float bj = c_s[O_B_IN + j];
                float4 w0 = ld4c(O_WIN_T + j * 8);
                float4 w1 = ld4c(O_WIN_T + j * 8 + 4);
                float va = bj, vb = bj;
                va = fmaf(xa[0], w0.x, va); vb = fmaf(xb[0], w0.x, vb);
                va = fmaf(xa[1], w0.y, va); vb = fmaf(xb[1], w0.y, vb);
                va = fmaf(xa[2], w0.z, va); vb = fmaf(xb[2], w0.z, vb);
                va = fmaf(xa[3], w0.w, va); vb = fmaf(xb[3], w0.w, vb);
                va = fmaf(xa[4], w1.x, va); vb = fmaf(xb[4], w1.x, vb);
                va = fmaf(xa[5], w1.y, va); vb = fmaf(xb[5], w1.y, vb);
                va = fmaf(xa[6], w1.z, va); vb = fmaf(xb[6], w1.z, vb);
                va = fmaf(xa[7], w1.w, va); vb = fmaf(xb[7], w1.w, vb);
                va = rr(va); vb = rr(vb);
                float4 h = ld4c(O_W_H1 + j * 4);
                x[2*pp  ][0] = fmaf(va, h.x, x[2*pp  ][0]);
                x[2*pp  ][1] = fmaf(va, h.y, x[2*pp  ][1]);
                x[2*pp  ][2] = fmaf(va, h.z, x[2*pp  ][2]);
                x[2*pp  ][3] = fmaf(va, h.w, x[2*pp  ][3]);
                x[2*pp+1][0] = fmaf(vb, h.x, x[2*pp+1][0]);
                x[2*pp+1][1] = fmaf(vb, h.y, x[2*pp+1][1]);
                x[2*pp+1][2] = fmaf(vb, h.z, x[2*pp+1][2]);
                x[2*pp+1][3] = fmaf(vb, h.w, x[2*pp+1][3]);
            }
        }
    }

    float t[4][4];

    // ---- encoder residual blocks ----
    lin44<true,  false>(O_W_H2, O_B_H2, x, t);
    lin44<false, true >(O_W_H3, O_B_H3, t, x);
    lin44<true,  false>(O_W_H4, O_B_H4, x, t);
    lin44<false, true >(O_W_H5, O_B_H5, t, x);

    // ---- encode (4 -> 1) + store ----
    float e[4];
    {
        float4 we = ld4c(O_W_EN);
        float be = c_s[O_B_EN];
#pragma unroll
        for (int r = 0; r < 4; r++) {
            float v = be;
            v = fmaf(x[r][0], we.x, v); v = fmaf(x[r][1], we.y, v);
            v = fmaf(x[r][2], we.z, v); v = fmaf(x[r][3], we.w, v);
            e[r] = rr(v);
        }
    }
#pragma unroll
    for (int r = 0; r < 4; r++) {
        unsigned row = base + r * NTH;
        if (!GUARD || row < (unsigned)N) __stcs(out + row, e[r]);
    }

    // ---- h6 (1 -> 4) ----
    {
        float4 w6 = ld4c(O_W_H6);
        float4 b6 = ld4c(O_B_H6);
#pragma unroll
        for (int r = 0; r < 4; r++) {
            x[r][0] = rr(fmaf(e[r], w6.x, b6.x));
            x[r][1] = rr(fmaf(e[r], w6.y, b6.y));
            x[r][2] = rr(fmaf(e[r], w6.z, b6.z));
            x[r][3] = rr(fmaf(e[r], w6.w, b6.w));
        }
    }

    // ---- decoder residual blocks ----
    lin44<true,  false>(O_W_H7, O_B_H7, x, t);
    lin44<false, true >(O_W_H8, O_B_H8, t, x);
    lin44<true,  false>(O_W_H9, O_B_H9, x, t);
    lin44<false, true >(O_W_HA, O_B_HA, t, x);

    // ---- decode (4 -> 8) + store, 2 rows at a time (low tail liveness) ----
    float* __restrict__ dec = out + N;
#pragma unroll
    for (int pp = 0; pp < 2; pp++) {
        float4 b0 = ld4c(O_B_DE);
        float4 b1 = ld4c(O_B_DE + 4);
        float da[8], db[8];
        da[0]=b0.x; da[1]=b0.y; da[2]=b0.z; da[3]=b0.w;
        da[4]=b1.x; da[5]=b1.y; da[6]=b1.z; da[7]=b1.w;
#pragma unroll
        for (int j = 0; j < 8; j++) db[j] = da[j];
#pragma unroll
        for (int i = 0; i < 4; i++) {
            float4 w0 = ld4c(O_W_DE + i * 8);
            float4 w1 = ld4c(O_W_DE + i * 8 + 4);
            float va = x[2*pp][i], vb = x[2*pp+1][i];
            da[0] = fmaf(va, w0.x, da[0]); db[0] = fmaf(vb, w0.x, db[0]);
            da[1] = fmaf(va, w0.y, da[1]); db[1] = fmaf(vb, w0.y, db[1]);
            da[2] = fmaf(va, w0.z, da[2]); db[2] = fmaf(vb, w0.z, db[2]);
            da[3] = fmaf(va, w0.w, da[3]); db[3] = fmaf(vb, w0.w, db[3]);
            da[4] = fmaf(va, w1.x, da[4]); db[4] = fmaf(vb, w1.x, db[4]);
            da[5] = fmaf(va, w1.y, da[5]); db[5] = fmaf(vb, w1.y, db[5]);
            da[6] = fmaf(va, w1.z, da[6]); db[6] = fmaf(vb, w1.z, db[6]);
            da[7] = fmaf(va, w1.w, da[7]); db[7] = fmaf(vb, w1.w, db[7]);
        }
        unsigned rA = base + (2 * pp) * NTH;
        unsigned rB = rA + NTH;
        if (!GUARD || rA < (unsigned)N) {
            __stcs(reinterpret_cast<float4*>(dec + (size_t)rA * 8),
                   make_float4(rr(da[0]), rr(da[1]), rr(da[2]), rr(da[3])));
            __stcs(reinterpret_cast<float4*>(dec + (size_t)rA * 8 + 4),
                   make_float4(rr(da[4]), rr(da[5]), rr(da[6]), rr(da[7])));
        }
        if (!GUARD || rB < (unsigned)N) {
            __stcs(reinterpret_cast<float4*>(dec + (size_t)rB * 8),
                   make_float4(rr(db[0]), rr(db[1]), rr(db[2]), rr(db[3])));
            __stcs(reinterpret_cast<float4*>(dec + (size_t)rB * 8 + 4),
                   make_float4(rr(db[4]), rr(db[5]), rr(db[6]), rr(db[7])));
        }
    }
}

extern "C" void kernel_launch(void* const* d_in, const int* in_sizes, int n_in,
                              void* d_out, int out_size) {
    Params P;
    for (int k = 0; k < 27; k++) P.p[k] = (const float*)d_in[k];
    int N = in_sizes[0] / 8;                 // 4194304 rows

    // 1) pack weights into staging buffer (1 round trip, fully parallel),
    // 2) copy into __constant__, 3) run the fused kernel.
    gather_weights<<<1, 352>>>(P);
    void* stage_ptr = nullptr;
    cudaGetSymbolAddress(&stage_ptr, g_stage);
    cudaMemcpyToSymbolAsync(c_s, stage_ptr, S_TOTAL * sizeof(float), 0,
                            cudaMemcpyDeviceToDevice, 0);

    int rows_per_block = 4 * NTH;            // 1024
    int blocks = (N + rows_per_block - 1) / rows_per_block;
    if (N % rows_per_block == 0)
        ann_fused_kernel<false><<<blocks, NTH>>>((const float*)d_in[0], (float*)d_out, N);
    else
        ann_fused_kernel<true ><<<blocks, NTH>>>((const float*)d_in[0], (float*)d_out, N);
}